// round 14
// baseline (speedup 1.0000x reference)
#include <cuda_runtime.h>
#include <cstdint>

// KMISCoarsening: persistent mega-kernel.
//  - proven plain atomicInc/gen 120-block barrier
//  - all-block full-sweep MIS (warp-per-node) while survivors >= THRESH
//  - crew A (blocks 0..7): MIS tail (warp-per-node, global frontier, 8-block
//    barrier) -> cluster -> fused pooling scatter, ALL hidden under
//    blocks 8..119 zeroing the 420MB adjc region
//  - outX (5MB) zeroed in phase 0; post-rendezvous = adjc scatter + divide
//    (fused, no final barrier)

#define N_NODES 10240
#define N_EDGES (N_NODES * 32)
#define DIM 128
#define EPS_F 0.5f
#define NBLK 120
#define NTHR 1024
#define THRESH 2560
#define CREWA 8
#define NTHRA (CREWA * NTHR)

// float4 count of adjc region (zeroed by crew B)
#define NQ_ADJC ((size_t)N_NODES * N_NODES / 4)      // 26,214,400
// float4 count of outX region (zeroed in phase 0)
#define NQ_OUTX ((size_t)N_NODES * DIM / 4)          // 327,680

// -------- device scratch (static: no allocations allowed) --------
__device__ int            g_mr[N_NODES];
__device__ unsigned char  g_mis[N_NODES];
__device__ float          g_deg[N_NODES];
__device__ int            g_cnt_row[N_NODES];
__device__ int            g_cnt_col[N_NODES];
__device__ int            g_row_start[N_NODES + 1];
__device__ int            g_col_start[N_NODES + 1];
__device__ int            g_fill_row[N_NODES];
__device__ int            g_fill_col[N_NODES];
__device__ int            g_csr_col[N_EDGES];
__device__ float          g_csr_val[N_EDGES];
__device__ int            g_csc_row[N_EDGES];
__device__ int            g_cluster[N_NODES];
__device__ float          g_counts[N_NODES];
__device__ int            g_front[2][N_NODES];
__device__ int            g_fcnt[2];
__device__ unsigned       g_bar_count = 0;
__device__ volatile unsigned g_bar_gen = 0;
__device__ unsigned       g_barA_count = 0;
__device__ volatile unsigned g_barA_gen = 0;
__device__ int            g_nc[2];

// -------- proven atomicInc/gen software barrier (parametrized) --------
__device__ __forceinline__ void barrier_impl(unsigned* cnt, volatile unsigned* gen_p,
                                             unsigned nblk) {
    __syncthreads();
    if (threadIdx.x == 0) {
        unsigned gen = *gen_p;
        __threadfence();  // publish this block's writes + order the gen read
        unsigned ticket = atomicInc(cnt, nblk - 1);
        if (ticket == nblk - 1) {
            __threadfence();
            *gen_p = gen + 1;
        } else {
            while (*gen_p == gen) { }
        }
        __threadfence();  // invalidate L1 before post-barrier reads
    }
    __syncthreads();
}
__device__ __forceinline__ void grid_barrier()  { barrier_impl(&g_bar_count,  &g_bar_gen,  NBLK); }
__device__ __forceinline__ void crewA_barrier() { barrier_impl(&g_barA_count, &g_barA_gen, CREWA); }

// Exclusive scan of N_NODES ints by ONE block of 1024 threads.
__device__ void block_scan(const int* __restrict__ cnt, int* __restrict__ start) {
    __shared__ int sh[NTHR];
    const int t = threadIdx.x;
    const int PER = N_NODES / NTHR;  // 10
    int base = t * PER;
    int s = 0;
#pragma unroll
    for (int j = 0; j < PER; j++) s += cnt[base + j];
    sh[t] = s;
    __syncthreads();
    for (int off = 1; off < NTHR; off <<= 1) {
        int v = 0;
        if (t >= off) v = sh[t - off];
        __syncthreads();
        if (t >= off) sh[t] += v;
        __syncthreads();
    }
    int run = sh[t] - s;  // exclusive prefix
#pragma unroll
    for (int j = 0; j < PER; j++) { start[base + j] = run; run += cnt[base + j]; }
    if (t == NTHR - 1) start[N_NODES] = run;
}

__global__ void __launch_bounds__(NTHR, 1)
kmis_mega_kernel(const float* __restrict__ x,
                 const float* __restrict__ attr,
                 const float* __restrict__ u,
                 const int*   __restrict__ ei,
                 const int*   __restrict__ rnk,
                 float*       __restrict__ out)
{
    const int tid  = threadIdx.x;
    const int gtid = blockIdx.x * blockDim.x + tid;
    const int nthr = gridDim.x * blockDim.x;
    const int* row = ei;
    const int* col = ei + N_EDGES;

    float* outX = out;                                        // (N, D)
    float* adjc = out + (size_t)N_NODES * DIM;                // (N, N)
    float* omis = adjc + (size_t)N_NODES * N_NODES;           // (N,)
    float* oclu = omis + N_NODES;                             // (N,)

    __shared__ int s_nc;

    // ---- phase 0: init scratch + zero outX (5MB) ----
    for (int i = gtid; i < N_NODES; i += nthr) {
        g_mr[i] = rnk[i];
        g_mis[i] = 0;
        g_deg[i] = 0.f;
        g_cnt_row[i] = 0; g_cnt_col[i] = 0;
        g_fill_row[i] = 0; g_fill_col[i] = 0;
        g_counts[i] = 0.f;
    }
    {
        float4* zx = reinterpret_cast<float4*>(outX);
        const float4 zv = make_float4(0.f, 0.f, 0.f, 0.f);
        for (size_t i = gtid; i < NQ_OUTX; i += nthr) zx[i] = zv;
    }
    if (gtid == 0) { g_fcnt[0] = 0; g_fcnt[1] = 0; }
    grid_barrier();   // init must complete before histogram atomics

    // ---- phase 0b: degree + row/col histograms ----
    for (int e = gtid; e < N_EDGES; e += nthr) {
        int r = row[e], c = col[e];
        atomicAdd(&g_deg[r], attr[e]);
        atomicAdd(&g_cnt_row[r], 1);
        atomicAdd(&g_cnt_col[c], 1);
    }
    grid_barrier();

    // ---- phase 0c: prefix sums ----
    if (blockIdx.x == 0)       block_scan(g_cnt_row, g_row_start);
    else if (blockIdx.x == 1)  block_scan(g_cnt_col, g_col_start);
    grid_barrier();

    // ---- phase 0d: fill CSR (col,val) and CSC (row) ----
    for (int e = gtid; e < N_EDGES; e += nthr) {
        int r = row[e], c = col[e];
        float d = g_deg[r];
        d = (d == 0.f) ? 1.f : d;
        float rv = (1.0f - EPS_F) * attr[e] / d;
        int p = g_row_start[r] + atomicAdd(&g_fill_row[r], 1);
        g_csr_col[p] = c;
        g_csr_val[p] = rv;
        int q = g_col_start[c] + atomicAdd(&g_fill_col[c], 1);
        g_csc_row[q] = r;
    }
    grid_barrier();

    // ---- MIS: all-block full sweeps (warp-per-node) while survivors >= THRESH ----
    const int wid = gtid >> 5, lane = gtid & 31, nwarp = nthr >> 5;
    int survivors = N_NODES;
    for (int it = 0; it < 512; ++it) {
        if (gtid == 0) g_nc[it & 1] = 0;
        for (int v = wid; v < N_NODES; v += nwarp) {
            int m = g_mr[v];
            if (m == N_NODES) continue;  // covered: can never join MIS
            int s0 = g_col_start[v], s1 = g_col_start[v + 1];
            for (int e = s0 + lane; e < s1; e += 32) m = min(m, g_mr[g_csc_row[e]]);
#pragma unroll
            for (int o = 16; o; o >>= 1) m = min(m, __shfl_xor_sync(0xffffffffu, m, o));
            if (lane == 0 && rnk[v] == m) g_mis[v] = 1;
        }
        grid_barrier();
        if (tid == 0) s_nc = 0;
        __syncthreads();
        for (int v = wid; v < N_NODES; v += nwarp) {
            if (g_mr[v] == N_NODES) continue;
            int cov = g_mis[v];
            int s0 = g_col_start[v], s1 = g_col_start[v + 1];
            for (int e = s0 + lane; e < s1 && !cov; e += 32) cov |= g_mis[g_csc_row[e]];
            cov = __any_sync(0xffffffffu, cov);
            if (lane == 0) {
                if (cov) g_mr[v] = N_NODES;
                else     atomicAdd(&s_nc, 1);
            }
        }
        __syncthreads();
        if (tid == 0 && s_nc != 0) atomicAdd(&g_nc[it & 1], s_nc);
        grid_barrier();
        survivors = *(volatile int*)&g_nc[it & 1];
        if (survivors < THRESH) break;   // uniform across blocks
    }

    if (blockIdx.x < CREWA) {
        // ============ crew A: MIS tail -> cluster -> fused pooling ============
        const int gA = blockIdx.x * NTHR + tid;
        const int widA = gA >> 5, nwarpA = NTHRA >> 5;

        if (survivors > 0) {
            // build frontier of uncovered nodes (g_fcnt[0]==0 from phase 0)
            for (int i = gA; i < N_NODES; i += NTHRA)
                if (g_mr[i] != N_NODES) g_front[0][atomicAdd(&g_fcnt[0], 1)] = i;
            crewA_barrier();

            int cur = 0;
            while (1) {
                int fc = g_fcnt[cur];
                if (fc == 0) break;
                // P1: warp-per-node over frontier
                for (int fi = widA; fi < fc; fi += nwarpA) {
                    int v = g_front[cur][fi];
                    int m = g_mr[v];  // == rank[v]
                    int s0 = g_col_start[v], s1 = g_col_start[v + 1];
                    for (int e = s0 + lane; e < s1; e += 32) m = min(m, g_mr[g_csc_row[e]]);
#pragma unroll
                    for (int o = 16; o; o >>= 1) m = min(m, __shfl_xor_sync(0xffffffffu, m, o));
                    if (lane == 0 && rnk[v] == m) g_mis[v] = 1;
                }
                if (gA == 0) g_fcnt[cur ^ 1] = 0;   // slot last read 2 phases ago
                crewA_barrier();
                // P2: coverage; survivors -> next frontier
                for (int fi = widA; fi < fc; fi += nwarpA) {
                    int v = g_front[cur][fi];
                    int cov = g_mis[v];
                    int s0 = g_col_start[v], s1 = g_col_start[v + 1];
                    for (int e = s0 + lane; e < s1 && !cov; e += 32) cov |= g_mis[g_csc_row[e]];
                    cov = __any_sync(0xffffffffu, cov);
                    if (lane == 0) {
                        if (cov) g_mr[v] = N_NODES;
                        else     g_front[cur ^ 1][atomicAdd(&g_fcnt[cur ^ 1], 1)] = v;
                    }
                }
                crewA_barrier();
                cur ^= 1;
            }
        }

        // ---- cluster + fused pooling scatter (crew A only) ----
        for (int i = gA; i < N_NODES; i += NTHRA) {
            int s0 = g_row_start[i], s1 = g_row_start[i + 1];
            bool mi = (g_mis[i] != 0);

            float rowsum = 0.f;
            for (int e = s0; e < s1; ++e)
                if (g_mis[g_csr_col[e]]) rowsum += g_csr_val[e];
            if (mi) rowsum += EPS_F;
            float rs = (rowsum == 0.f) ? 1.f : rowsum;

            // pass 1: total of normalized masses in ascending-column order
            float total = 0.f;
            int prev = -1;
            while (1) {
                int jm = 0x7fffffff;
                if (mi && i > prev) jm = i;
                for (int e = s0; e < s1; ++e) {
                    int c = g_csr_col[e];
                    if (c > prev && c < jm && g_mis[c]) jm = c;
                }
                if (jm == 0x7fffffff) break;
                float mass = 0.f;
                for (int e = s0; e < s1; ++e)
                    if (g_csr_col[e] == jm) mass += g_csr_val[e];
                if (jm == i && mi) mass += EPS_F;
                total += mass / rs;
                prev = jm;
            }
            float T = u[i] * total;

            // pass 2: first column whose normalized CDF exceeds T
            int res = 0;
            prev = -1;
            float acc = 0.f;
            while (1) {
                int jm = 0x7fffffff;
                if (mi && i > prev) jm = i;
                for (int e = s0; e < s1; ++e) {
                    int c = g_csr_col[e];
                    if (c > prev && c < jm && g_mis[c]) jm = c;
                }
                if (jm == 0x7fffffff) break;
                float mass = 0.f;
                for (int e = s0; e < s1; ++e)
                    if (g_csr_col[e] == jm) mass += g_csr_val[e];
                if (jm == i && mi) mass += EPS_F;
                acc += mass / rs;
                if (acc > T) { res = jm; break; }
                prev = jm;
            }

            g_cluster[i] = res;
            atomicAdd(&g_counts[res], 1.0f);
            omis[i] = mi ? 1.0f : 0.0f;
            oclu[i] = (float)res;

            // fused pooling: x[i] -> outX[res] (outX zeroed in phase 0)
            const float4* xv4 = reinterpret_cast<const float4*>(x) + (size_t)i * (DIM / 4);
            float* dst = outX + (size_t)res * DIM;
#pragma unroll 4
            for (int q = 0; q < DIM / 4; ++q) {
                float4 v = xv4[q];
                atomicAdd(dst + q * 4 + 0, v.x);
                atomicAdd(dst + q * 4 + 1, v.y);
                atomicAdd(dst + q * 4 + 2, v.z);
                atomicAdd(dst + q * 4 + 3, v.w);
            }
        }
    } else {
        // ============ crew B: stream-zero adjc (420MB) ============
        float4* zdst = reinterpret_cast<float4*>(adjc);
        const float4 zv = make_float4(0.f, 0.f, 0.f, 0.f);
        const size_t start  = (size_t)(blockIdx.x - CREWA) * NTHR + tid;
        const size_t stride = (size_t)(NBLK - CREWA) * NTHR;
        for (size_t i = start; i < NQ_ADJC; i += stride) __stcs(zdst + i, zv);
    }

    grid_barrier();   // rendezvous: cluster/pool/omis/oclu + adjc zeros visible

    // ---- adjc scatter + divide (fused; independent targets; no final barrier) ----
    for (int e = gtid; e < N_EDGES; e += nthr) {
        int r = row[e], c = col[e];
        atomicAdd(&adjc[(size_t)g_cluster[r] * N_NODES + g_cluster[c]], attr[e]);
    }
    for (int idx = gtid; idx < N_NODES * (DIM / 4); idx += nthr) {
        int i = idx >> 5;
        float cm = fmaxf(g_counts[i], 1.0f);
        float4 v = reinterpret_cast<float4*>(outX)[idx];
        v.x = v.x / cm; v.y = v.y / cm; v.z = v.z / cm; v.w = v.w / cm;
        reinterpret_cast<float4*>(outX)[idx] = v;
    }
}

extern "C" void kernel_launch(void* const* d_in, const int* in_sizes, int n_in,
                              void* d_out, int out_size) {
    const float* x    = (const float*)d_in[0];  // (N, D)
    const float* attr = (const float*)d_in[1];  // (E,)
    const float* u    = (const float*)d_in[2];  // (N,)
    const int*   ei   = (const int*)  d_in[3];  // (2, E)
    const int*   rnk  = (const int*)  d_in[4];  // (N,)
    float* out = (float*)d_out;

    kmis_mega_kernel<<<NBLK, NTHR>>>(x, attr, u, ei, rnk, out);
}

// round 15
// speedup vs baseline: 1.4854x; 1.4854x over previous
#include <cuda_runtime.h>
#include <cstdint>

// KMISCoarsening: persistent mega-kernel (R12 structure, best known = 307us).
// Changes vs R12:
//  (1) THRESH/TAILCAP 2560 -> 5120 (all-block MIS: 2 iters -> 1; tail still
//      warp-per-node smem worklist, syncthreads-only under the zero flood)
//  (2) divide pass + final barrier eliminated: pooling scatters x_i * inv_c
//      (counts final after cluster barrier); pooling fused with adjc scatter
//  (3) outX zeroed in phase 0; zero crew handles only adjc (420MB)
// RULE (4x confirmed): never run global-atomic barrier spins concurrently
// with the store flood -- only smem-sync'd block-0 tail overlaps it.

#define N_NODES 10240
#define N_EDGES (N_NODES * 32)
#define DIM 128
#define EPS_F 0.5f
#define NBLK 120
#define NTHR 1024
#define THRESH 5120     // handoff when survivors drop below this
#define TAILCAP 5120    // smem worklist capacity (>= THRESH)

#define NQ_ADJC ((size_t)N_NODES * N_NODES / 4)      // 26,214,400 float4
#define NQ_OUTX ((size_t)N_NODES * DIM / 4)          // 327,680 float4

// -------- device scratch (static: no allocations allowed) --------
__device__ int            g_mr[N_NODES];
__device__ unsigned char  g_mis[N_NODES];
__device__ float          g_deg[N_NODES];
__device__ int            g_cnt_row[N_NODES];
__device__ int            g_cnt_col[N_NODES];
__device__ int            g_row_start[N_NODES + 1];
__device__ int            g_col_start[N_NODES + 1];
__device__ int            g_fill_row[N_NODES];
__device__ int            g_fill_col[N_NODES];
__device__ int            g_csr_col[N_EDGES];
__device__ float          g_csr_val[N_EDGES];
__device__ int            g_csc_row[N_EDGES];
__device__ int            g_cluster[N_NODES];
__device__ float          g_counts[N_NODES];
__device__ unsigned       g_bar_count = 0;
__device__ volatile unsigned g_bar_gen = 0;
__device__ int            g_nc[2];

// -------- proven atomicInc/gen software grid barrier --------
__device__ __forceinline__ void grid_barrier() {
    __syncthreads();
    if (threadIdx.x == 0) {
        unsigned gen = g_bar_gen;
        __threadfence();  // publish this block's writes + order the gen read
        unsigned ticket = atomicInc(&g_bar_count, (unsigned)(gridDim.x - 1));
        if (ticket == (unsigned)(gridDim.x - 1)) {
            __threadfence();
            g_bar_gen = gen + 1;
        } else {
            while (g_bar_gen == gen) { }
        }
        __threadfence();  // invalidate L1 before post-barrier reads
    }
    __syncthreads();
}

// Exclusive scan of N_NODES ints by ONE block of 1024 threads.
__device__ void block_scan(const int* __restrict__ cnt, int* __restrict__ start) {
    __shared__ int sh[NTHR];
    const int t = threadIdx.x;
    const int PER = N_NODES / NTHR;  // 10
    int base = t * PER;
    int s = 0;
#pragma unroll
    for (int j = 0; j < PER; j++) s += cnt[base + j];
    sh[t] = s;
    __syncthreads();
    for (int off = 1; off < NTHR; off <<= 1) {
        int v = 0;
        if (t >= off) v = sh[t - off];
        __syncthreads();
        if (t >= off) sh[t] += v;
        __syncthreads();
    }
    int run = sh[t] - s;  // exclusive prefix
#pragma unroll
    for (int j = 0; j < PER; j++) { start[base + j] = run; run += cnt[base + j]; }
    if (t == NTHR - 1) start[N_NODES] = run;
}

__global__ void __launch_bounds__(NTHR, 1)
kmis_mega_kernel(const float* __restrict__ x,
                 const float* __restrict__ attr,
                 const float* __restrict__ u,
                 const int*   __restrict__ ei,
                 const int*   __restrict__ rnk,
                 float*       __restrict__ out)
{
    const int tid  = threadIdx.x;
    const int gtid = blockIdx.x * blockDim.x + tid;
    const int nthr = gridDim.x * blockDim.x;
    const int* row = ei;
    const int* col = ei + N_EDGES;

    float* outX = out;                                        // (N, D)
    float* adjc = out + (size_t)N_NODES * DIM;                // (N, N)
    float* omis = adjc + (size_t)N_NODES * N_NODES;           // (N,)
    float* oclu = omis + N_NODES;                             // (N,)

    __shared__ int s_nc;

    // ---- phase 0: init scratch + zero outX (5MB) ----
    for (int i = gtid; i < N_NODES; i += nthr) {
        g_mr[i] = rnk[i];
        g_mis[i] = 0;
        g_deg[i] = 0.f;
        g_cnt_row[i] = 0; g_cnt_col[i] = 0;
        g_fill_row[i] = 0; g_fill_col[i] = 0;
        g_counts[i] = 0.f;
    }
    {
        float4* zx = reinterpret_cast<float4*>(outX);
        const float4 zv = make_float4(0.f, 0.f, 0.f, 0.f);
        for (size_t i = gtid; i < NQ_OUTX; i += nthr) zx[i] = zv;
    }
    grid_barrier();   // init must complete before histogram atomics

    // ---- phase 0b: degree + row/col histograms ----
    for (int e = gtid; e < N_EDGES; e += nthr) {
        int r = row[e], c = col[e];
        atomicAdd(&g_deg[r], attr[e]);
        atomicAdd(&g_cnt_row[r], 1);
        atomicAdd(&g_cnt_col[c], 1);
    }
    grid_barrier();

    // ---- phase 0c: prefix sums ----
    if (blockIdx.x == 0)       block_scan(g_cnt_row, g_row_start);
    else if (blockIdx.x == 1)  block_scan(g_cnt_col, g_col_start);
    grid_barrier();

    // ---- phase 0d: fill CSR (col,val) and CSC (row) ----
    for (int e = gtid; e < N_EDGES; e += nthr) {
        int r = row[e], c = col[e];
        float d = g_deg[r];
        d = (d == 0.f) ? 1.f : d;
        float rv = (1.0f - EPS_F) * attr[e] / d;
        int p = g_row_start[r] + atomicAdd(&g_fill_row[r], 1);
        g_csr_col[p] = c;
        g_csr_val[p] = rv;
        int q = g_col_start[c] + atomicAdd(&g_fill_col[c], 1);
        g_csc_row[q] = r;
    }
    grid_barrier();

    // ---- MIS: all-block full sweeps (warp-per-node) while survivors >= THRESH ----
    const int wid = gtid >> 5, lane = gtid & 31, nwarp = nthr >> 5;
    int survivors = N_NODES;
    for (int it = 0; it < 512; ++it) {
        if (gtid == 0) g_nc[it & 1] = 0;
        for (int v = wid; v < N_NODES; v += nwarp) {
            int m = g_mr[v];
            if (m == N_NODES) continue;  // covered: can never join MIS
            int s0 = g_col_start[v], s1 = g_col_start[v + 1];
            for (int e = s0 + lane; e < s1; e += 32) m = min(m, g_mr[g_csc_row[e]]);
#pragma unroll
            for (int o = 16; o; o >>= 1) m = min(m, __shfl_xor_sync(0xffffffffu, m, o));
            if (lane == 0 && rnk[v] == m) g_mis[v] = 1;
        }
        grid_barrier();
        if (tid == 0) s_nc = 0;
        __syncthreads();
        for (int v = wid; v < N_NODES; v += nwarp) {
            if (g_mr[v] == N_NODES) continue;
            int cov = g_mis[v];
            int s0 = g_col_start[v], s1 = g_col_start[v + 1];
            for (int e = s0 + lane; e < s1 && !cov; e += 32) cov |= g_mis[g_csc_row[e]];
            cov = __any_sync(0xffffffffu, cov);
            if (lane == 0) {
                if (cov) g_mr[v] = N_NODES;
                else     atomicAdd(&s_nc, 1);
            }
        }
        __syncthreads();
        if (tid == 0 && s_nc != 0) atomicAdd(&g_nc[it & 1], s_nc);
        grid_barrier();
        survivors = *(volatile int*)&g_nc[it & 1];
        if (survivors < THRESH) break;   // uniform across blocks
    }

    // ---- split: block 0 finishes MIS tail (smem worklist, WARP-per-node,
    //      syncthreads-only); blocks 1..119 stream-zero adjc concurrently ----
    if (blockIdx.x == 0 && survivors > 0) {
        __shared__ int s_list[2][TAILCAP];
        __shared__ int s_cnt[2];
        const int wl = tid >> 5;  // warp id in block, 0..31

        // build worklist of uncovered nodes
        if (tid < 2) s_cnt[tid] = 0;
        __syncthreads();
        for (int i = tid; i < N_NODES; i += NTHR)
            if (g_mr[i] != N_NODES) s_list[0][atomicAdd(&s_cnt[0], 1)] = i;
        __syncthreads();

        int cur = 0;
        while (s_cnt[cur] > 0) {
            int fc = s_cnt[cur];
            // P1 over worklist (warp-per-node, strided lanes -> 32-way MLP)
            for (int fi = wl; fi < fc; fi += 32) {
                int v = s_list[cur][fi];
                int m = g_mr[v];  // == rank[v]
                int s0 = g_col_start[v], s1 = g_col_start[v + 1];
                for (int e = s0 + lane; e < s1; e += 32) m = min(m, g_mr[g_csc_row[e]]);
#pragma unroll
                for (int o = 16; o; o >>= 1) m = min(m, __shfl_xor_sync(0xffffffffu, m, o));
                if (lane == 0 && rnk[v] == m) g_mis[v] = 1;
            }
            __syncthreads();
            if (tid == 0) s_cnt[cur ^ 1] = 0;
            __syncthreads();
            // P2 over worklist; survivors -> next worklist
            for (int fi = wl; fi < fc; fi += 32) {
                int v = s_list[cur][fi];
                int cov = g_mis[v];
                int s0 = g_col_start[v], s1 = g_col_start[v + 1];
                for (int e = s0 + lane; e < s1 && !cov; e += 32) cov |= g_mis[g_csc_row[e]];
                cov = __any_sync(0xffffffffu, cov);
                if (lane == 0) {
                    if (cov) g_mr[v] = N_NODES;
                    else     s_list[cur ^ 1][atomicAdd(&s_cnt[cur ^ 1], 1)] = v;
                }
            }
            __syncthreads();
            cur ^= 1;
        }
    } else if (blockIdx.x > 0) {
        // stream-zero adjc (420MB) with 119 blocks
        float4* zdst = reinterpret_cast<float4*>(adjc);
        const float4 zv = make_float4(0.f, 0.f, 0.f, 0.f);
        const size_t start  = (size_t)(blockIdx.x - 1) * NTHR + tid;
        const size_t stride = (size_t)(NBLK - 1) * NTHR;
        for (size_t i = start; i < NQ_ADJC; i += stride) __stcs(zdst + i, zv);
    }

    grid_barrier();   // rendezvous: final MIS + adjc zeros visible everywhere

    // ---- cluster phase: per-row multinomial via sorted sparse CDF traversal ----
    for (int i = gtid; i < N_NODES; i += nthr) {
        int s0 = g_row_start[i], s1 = g_row_start[i + 1];
        bool mi = (g_mis[i] != 0);

        float rowsum = 0.f;
        for (int e = s0; e < s1; ++e)
            if (g_mis[g_csr_col[e]]) rowsum += g_csr_val[e];
        if (mi) rowsum += EPS_F;
        float rs = (rowsum == 0.f) ? 1.f : rowsum;

        // pass 1: total of normalized masses in ascending-column order
        float total = 0.f;
        int prev = -1;
        while (1) {
            int jm = 0x7fffffff;
            if (mi && i > prev) jm = i;
            for (int e = s0; e < s1; ++e) {
                int c = g_csr_col[e];
                if (c > prev && c < jm && g_mis[c]) jm = c;
            }
            if (jm == 0x7fffffff) break;
            float mass = 0.f;
            for (int e = s0; e < s1; ++e)
                if (g_csr_col[e] == jm) mass += g_csr_val[e];
            if (jm == i && mi) mass += EPS_F;
            total += mass / rs;
            prev = jm;
        }
        float T = u[i] * total;

        // pass 2: first column whose normalized CDF exceeds T
        int res = 0;
        prev = -1;
        float acc = 0.f;
        while (1) {
            int jm = 0x7fffffff;
            if (mi && i > prev) jm = i;
            for (int e = s0; e < s1; ++e) {
                int c = g_csr_col[e];
                if (c > prev && c < jm && g_mis[c]) jm = c;
            }
            if (jm == 0x7fffffff) break;
            float mass = 0.f;
            for (int e = s0; e < s1; ++e)
                if (g_csr_col[e] == jm) mass += g_csr_val[e];
            if (jm == i && mi) mass += EPS_F;
            acc += mass / rs;
            if (acc > T) { res = jm; break; }
            prev = jm;
        }

        g_cluster[i] = res;
        atomicAdd(&g_counts[res], 1.0f);
        omis[i] = mi ? 1.0f : 0.0f;
        oclu[i] = (float)res;
    }
    grid_barrier();   // cluster + counts final

    // ---- fused: scaled pooling scatter (x_i * inv_c) + adjc scatter ----
    // out[c] = sum_i x_i / max(count_c,1): divide folded into the scatter,
    // so no divide pass and no final barrier.
    for (int idx = gtid; idx < N_NODES * (DIM / 4); idx += nthr) {
        int i = idx >> 5, q = idx & 31;
        int c = g_cluster[i];
        float inv = 1.0f / fmaxf(g_counts[c], 1.0f);
        float4 xv = reinterpret_cast<const float4*>(x)[idx];
        float* dst = outX + (size_t)c * DIM + q * 4;
        atomicAdd(dst + 0, xv.x * inv);
        atomicAdd(dst + 1, xv.y * inv);
        atomicAdd(dst + 2, xv.z * inv);
        atomicAdd(dst + 3, xv.w * inv);
    }
    for (int e = gtid; e < N_EDGES; e += nthr) {
        int r = row[e], c = col[e];
        atomicAdd(&adjc[(size_t)g_cluster[r] * N_NODES + g_cluster[c]], attr[e]);
    }
}

extern "C" void kernel_launch(void* const* d_in, const int* in_sizes, int n_in,
                              void* d_out, int out_size) {
    const float* x    = (const float*)d_in[0];  // (N, D)
    const float* attr = (const float*)d_in[1];  // (E,)
    const float* u    = (const float*)d_in[2];  // (N,)
    const int*   ei   = (const int*)  d_in[3];  // (2, E)
    const int*   rnk  = (const int*)  d_in[4];  // (N,)
    float* out = (float*)d_out;

    kmis_mega_kernel<<<NBLK, NTHR>>>(x, attr, u, ei, rnk, out);
}

// round 16
// speedup vs baseline: 2.1557x; 1.4513x over previous
#include <cuda_runtime.h>
#include <cstdint>

// KMISCoarsening: persistent mega-kernel (R12 structure + R14 fusions).
//  - THRESH/TAILCAP = 2560 (R12-proven; 5120 made the block-0 tail exceed the
//    zero window -- tail cost scales with survivors at handoff)
//  - tail: block 0, smem worklist, WARP-per-node, syncthreads-only, under
//    blocks 1..119 stream-zeroing adjc (420MB)
//  - fused scaled pooling (x_i * inv_c) + adjc scatter; no divide pass,
//    no final barrier; outX zeroed in phase 0
// RULE (4x confirmed): never run global-atomic barrier spins concurrently
// with the store flood.

#define N_NODES 10240
#define N_EDGES (N_NODES * 32)
#define DIM 128
#define EPS_F 0.5f
#define NBLK 120
#define NTHR 1024
#define THRESH 2560     // handoff when survivors drop below this
#define TAILCAP 2560    // smem worklist capacity (>= THRESH)

#define NQ_ADJC ((size_t)N_NODES * N_NODES / 4)      // 26,214,400 float4
#define NQ_OUTX ((size_t)N_NODES * DIM / 4)          // 327,680 float4

// -------- device scratch (static: no allocations allowed) --------
__device__ int            g_mr[N_NODES];
__device__ unsigned char  g_mis[N_NODES];
__device__ float          g_deg[N_NODES];
__device__ int            g_cnt_row[N_NODES];
__device__ int            g_cnt_col[N_NODES];
__device__ int            g_row_start[N_NODES + 1];
__device__ int            g_col_start[N_NODES + 1];
__device__ int            g_fill_row[N_NODES];
__device__ int            g_fill_col[N_NODES];
__device__ int            g_csr_col[N_EDGES];
__device__ float          g_csr_val[N_EDGES];
__device__ int            g_csc_row[N_EDGES];
__device__ int            g_cluster[N_NODES];
__device__ float          g_counts[N_NODES];
__device__ unsigned       g_bar_count = 0;
__device__ volatile unsigned g_bar_gen = 0;
__device__ int            g_nc[2];

// -------- proven atomicInc/gen software grid barrier --------
__device__ __forceinline__ void grid_barrier() {
    __syncthreads();
    if (threadIdx.x == 0) {
        unsigned gen = g_bar_gen;
        __threadfence();  // publish this block's writes + order the gen read
        unsigned ticket = atomicInc(&g_bar_count, (unsigned)(gridDim.x - 1));
        if (ticket == (unsigned)(gridDim.x - 1)) {
            __threadfence();
            g_bar_gen = gen + 1;
        } else {
            while (g_bar_gen == gen) { }
        }
        __threadfence();  // invalidate L1 before post-barrier reads
    }
    __syncthreads();
}

// Exclusive scan of N_NODES ints by ONE block of 1024 threads.
__device__ void block_scan(const int* __restrict__ cnt, int* __restrict__ start) {
    __shared__ int sh[NTHR];
    const int t = threadIdx.x;
    const int PER = N_NODES / NTHR;  // 10
    int base = t * PER;
    int s = 0;
#pragma unroll
    for (int j = 0; j < PER; j++) s += cnt[base + j];
    sh[t] = s;
    __syncthreads();
    for (int off = 1; off < NTHR; off <<= 1) {
        int v = 0;
        if (t >= off) v = sh[t - off];
        __syncthreads();
        if (t >= off) sh[t] += v;
        __syncthreads();
    }
    int run = sh[t] - s;  // exclusive prefix
#pragma unroll
    for (int j = 0; j < PER; j++) { start[base + j] = run; run += cnt[base + j]; }
    if (t == NTHR - 1) start[N_NODES] = run;
}

__global__ void __launch_bounds__(NTHR, 1)
kmis_mega_kernel(const float* __restrict__ x,
                 const float* __restrict__ attr,
                 const float* __restrict__ u,
                 const int*   __restrict__ ei,
                 const int*   __restrict__ rnk,
                 float*       __restrict__ out)
{
    const int tid  = threadIdx.x;
    const int gtid = blockIdx.x * blockDim.x + tid;
    const int nthr = gridDim.x * blockDim.x;
    const int* row = ei;
    const int* col = ei + N_EDGES;

    float* outX = out;                                        // (N, D)
    float* adjc = out + (size_t)N_NODES * DIM;                // (N, N)
    float* omis = adjc + (size_t)N_NODES * N_NODES;           // (N,)
    float* oclu = omis + N_NODES;                             // (N,)

    __shared__ int s_nc;

    // ---- phase 0: init scratch + zero outX (5MB) ----
    for (int i = gtid; i < N_NODES; i += nthr) {
        g_mr[i] = rnk[i];
        g_mis[i] = 0;
        g_deg[i] = 0.f;
        g_cnt_row[i] = 0; g_cnt_col[i] = 0;
        g_fill_row[i] = 0; g_fill_col[i] = 0;
        g_counts[i] = 0.f;
    }
    {
        float4* zx = reinterpret_cast<float4*>(outX);
        const float4 zv = make_float4(0.f, 0.f, 0.f, 0.f);
        for (size_t i = gtid; i < NQ_OUTX; i += nthr) zx[i] = zv;
    }
    grid_barrier();   // init must complete before histogram atomics

    // ---- phase 0b: degree + row/col histograms ----
    for (int e = gtid; e < N_EDGES; e += nthr) {
        int r = row[e], c = col[e];
        atomicAdd(&g_deg[r], attr[e]);
        atomicAdd(&g_cnt_row[r], 1);
        atomicAdd(&g_cnt_col[c], 1);
    }
    grid_barrier();

    // ---- phase 0c: prefix sums ----
    if (blockIdx.x == 0)       block_scan(g_cnt_row, g_row_start);
    else if (blockIdx.x == 1)  block_scan(g_cnt_col, g_col_start);
    grid_barrier();

    // ---- phase 0d: fill CSR (col,val) and CSC (row) ----
    for (int e = gtid; e < N_EDGES; e += nthr) {
        int r = row[e], c = col[e];
        float d = g_deg[r];
        d = (d == 0.f) ? 1.f : d;
        float rv = (1.0f - EPS_F) * attr[e] / d;
        int p = g_row_start[r] + atomicAdd(&g_fill_row[r], 1);
        g_csr_col[p] = c;
        g_csr_val[p] = rv;
        int q = g_col_start[c] + atomicAdd(&g_fill_col[c], 1);
        g_csc_row[q] = r;
    }
    grid_barrier();

    // ---- MIS: all-block full sweeps (warp-per-node) while survivors >= THRESH ----
    const int wid = gtid >> 5, lane = gtid & 31, nwarp = nthr >> 5;
    int survivors = N_NODES;
    for (int it = 0; it < 512; ++it) {
        if (gtid == 0) g_nc[it & 1] = 0;
        for (int v = wid; v < N_NODES; v += nwarp) {
            int m = g_mr[v];
            if (m == N_NODES) continue;  // covered: can never join MIS
            int s0 = g_col_start[v], s1 = g_col_start[v + 1];
            for (int e = s0 + lane; e < s1; e += 32) m = min(m, g_mr[g_csc_row[e]]);
#pragma unroll
            for (int o = 16; o; o >>= 1) m = min(m, __shfl_xor_sync(0xffffffffu, m, o));
            if (lane == 0 && rnk[v] == m) g_mis[v] = 1;
        }
        grid_barrier();
        if (tid == 0) s_nc = 0;
        __syncthreads();
        for (int v = wid; v < N_NODES; v += nwarp) {
            if (g_mr[v] == N_NODES) continue;
            int cov = g_mis[v];
            int s0 = g_col_start[v], s1 = g_col_start[v + 1];
            for (int e = s0 + lane; e < s1 && !cov; e += 32) cov |= g_mis[g_csc_row[e]];
            cov = __any_sync(0xffffffffu, cov);
            if (lane == 0) {
                if (cov) g_mr[v] = N_NODES;
                else     atomicAdd(&s_nc, 1);
            }
        }
        __syncthreads();
        if (tid == 0 && s_nc != 0) atomicAdd(&g_nc[it & 1], s_nc);
        grid_barrier();
        survivors = *(volatile int*)&g_nc[it & 1];
        if (survivors < THRESH) break;   // uniform across blocks
    }

    // ---- split: block 0 finishes MIS tail (smem worklist, WARP-per-node,
    //      syncthreads-only); blocks 1..119 stream-zero adjc concurrently ----
    if (blockIdx.x == 0 && survivors > 0) {
        __shared__ int s_list[2][TAILCAP];
        __shared__ int s_cnt[2];
        const int wl = tid >> 5;  // warp id in block, 0..31

        // build worklist of uncovered nodes
        if (tid < 2) s_cnt[tid] = 0;
        __syncthreads();
        for (int i = tid; i < N_NODES; i += NTHR)
            if (g_mr[i] != N_NODES) s_list[0][atomicAdd(&s_cnt[0], 1)] = i;
        __syncthreads();

        int cur = 0;
        while (s_cnt[cur] > 0) {
            int fc = s_cnt[cur];
            // P1 over worklist (warp-per-node, strided lanes -> 32-way MLP)
            for (int fi = wl; fi < fc; fi += 32) {
                int v = s_list[cur][fi];
                int m = g_mr[v];  // == rank[v]
                int s0 = g_col_start[v], s1 = g_col_start[v + 1];
                for (int e = s0 + lane; e < s1; e += 32) m = min(m, g_mr[g_csc_row[e]]);
#pragma unroll
                for (int o = 16; o; o >>= 1) m = min(m, __shfl_xor_sync(0xffffffffu, m, o));
                if (lane == 0 && rnk[v] == m) g_mis[v] = 1;
            }
            __syncthreads();
            if (tid == 0) s_cnt[cur ^ 1] = 0;
            __syncthreads();
            // P2 over worklist; survivors -> next worklist
            for (int fi = wl; fi < fc; fi += 32) {
                int v = s_list[cur][fi];
                int cov = g_mis[v];
                int s0 = g_col_start[v], s1 = g_col_start[v + 1];
                for (int e = s0 + lane; e < s1 && !cov; e += 32) cov |= g_mis[g_csc_row[e]];
                cov = __any_sync(0xffffffffu, cov);
                if (lane == 0) {
                    if (cov) g_mr[v] = N_NODES;
                    else     s_list[cur ^ 1][atomicAdd(&s_cnt[cur ^ 1], 1)] = v;
                }
            }
            __syncthreads();
            cur ^= 1;
        }
    } else if (blockIdx.x > 0) {
        // stream-zero adjc (420MB) with 119 blocks
        float4* zdst = reinterpret_cast<float4*>(adjc);
        const float4 zv = make_float4(0.f, 0.f, 0.f, 0.f);
        const size_t start  = (size_t)(blockIdx.x - 1) * NTHR + tid;
        const size_t stride = (size_t)(NBLK - 1) * NTHR;
        for (size_t i = start; i < NQ_ADJC; i += stride) __stcs(zdst + i, zv);
    }

    grid_barrier();   // rendezvous: final MIS + adjc zeros visible everywhere

    // ---- cluster phase: per-row multinomial via sorted sparse CDF traversal ----
    for (int i = gtid; i < N_NODES; i += nthr) {
        int s0 = g_row_start[i], s1 = g_row_start[i + 1];
        bool mi = (g_mis[i] != 0);

        float rowsum = 0.f;
        for (int e = s0; e < s1; ++e)
            if (g_mis[g_csr_col[e]]) rowsum += g_csr_val[e];
        if (mi) rowsum += EPS_F;
        float rs = (rowsum == 0.f) ? 1.f : rowsum;

        // pass 1: total of normalized masses in ascending-column order
        float total = 0.f;
        int prev = -1;
        while (1) {
            int jm = 0x7fffffff;
            if (mi && i > prev) jm = i;
            for (int e = s0; e < s1; ++e) {
                int c = g_csr_col[e];
                if (c > prev && c < jm && g_mis[c]) jm = c;
            }
            if (jm == 0x7fffffff) break;
            float mass = 0.f;
            for (int e = s0; e < s1; ++e)
                if (g_csr_col[e] == jm) mass += g_csr_val[e];
            if (jm == i && mi) mass += EPS_F;
            total += mass / rs;
            prev = jm;
        }
        float T = u[i] * total;

        // pass 2: first column whose normalized CDF exceeds T
        int res = 0;
        prev = -1;
        float acc = 0.f;
        while (1) {
            int jm = 0x7fffffff;
            if (mi && i > prev) jm = i;
            for (int e = s0; e < s1; ++e) {
                int c = g_csr_col[e];
                if (c > prev && c < jm && g_mis[c]) jm = c;
            }
            if (jm == 0x7fffffff) break;
            float mass = 0.f;
            for (int e = s0; e < s1; ++e)
                if (g_csr_col[e] == jm) mass += g_csr_val[e];
            if (jm == i && mi) mass += EPS_F;
            acc += mass / rs;
            if (acc > T) { res = jm; break; }
            prev = jm;
        }

        g_cluster[i] = res;
        atomicAdd(&g_counts[res], 1.0f);
        omis[i] = mi ? 1.0f : 0.0f;
        oclu[i] = (float)res;
    }
    grid_barrier();   // cluster + counts final

    // ---- fused: scaled pooling scatter (x_i * inv_c) + adjc scatter ----
    // out[c] = sum_i x_i / max(count_c,1): divide folded into the scatter,
    // so no divide pass and no final barrier.
    for (int idx = gtid; idx < N_NODES * (DIM / 4); idx += nthr) {
        int i = idx >> 5, q = idx & 31;
        int c = g_cluster[i];
        float inv = 1.0f / fmaxf(g_counts[c], 1.0f);
        float4 xv = reinterpret_cast<const float4*>(x)[idx];
        float* dst = outX + (size_t)c * DIM + q * 4;
        atomicAdd(dst + 0, xv.x * inv);
        atomicAdd(dst + 1, xv.y * inv);
        atomicAdd(dst + 2, xv.z * inv);
        atomicAdd(dst + 3, xv.w * inv);
    }
    for (int e = gtid; e < N_EDGES; e += nthr) {
        int r = row[e], c = col[e];
        atomicAdd(&adjc[(size_t)g_cluster[r] * N_NODES + g_cluster[c]], attr[e]);
    }
}

extern "C" void kernel_launch(void* const* d_in, const int* in_sizes, int n_in,
                              void* d_out, int out_size) {
    const float* x    = (const float*)d_in[0];  // (N, D)
    const float* attr = (const float*)d_in[1];  // (E,)
    const float* u    = (const float*)d_in[2];  // (N,)
    const int*   ei   = (const int*)  d_in[3];  // (2, E)
    const int*   rnk  = (const int*)  d_in[4];  // (N,)
    float* out = (float*)d_out;

    kmis_mega_kernel<<<NBLK, NTHR>>>(x, attr, u, ei, rnk, out);
}